// round 17
// baseline (speedup 1.0000x reference)
#include <cuda_runtime.h>
#include <cuda_bf16.h>
#include <cstdint>

#define CH    512
#define HW    4096
#define SCALE (1.0e6f / 33554432.0f)
#define NA    144     // kernel A CTAs: 36 upper-tri 64x64 tiles x splitK 4

__device__ __align__(16) __nv_bfloat16 g_feats[CH * HW];  // 4 MB bf16 feats
__device__ __align__(16) float g_G[CH * CH];              // gram (scaled 1/2^20)
__device__ unsigned int g_barA;   // monotonic, +NA per launch

// ---------------------------------------------------------------------------
__device__ __forceinline__ uint32_t smem_u32(const void* p) {
    return static_cast<uint32_t>(__cvta_generic_to_shared(p));
}
__device__ __forceinline__ void cp_async16(uint32_t dst, const void* src) {
    asm volatile("cp.async.cg.shared.global [%0], [%1], 16;\n" :: "r"(dst), "l"(src));
}
template <int N>
__device__ __forceinline__ void cp_wait() {
    asm volatile("cp.async.wait_group %0;\n" :: "n"(N) : "memory");
}
__device__ __forceinline__ void cp_commit() {
    asm volatile("cp.async.commit_group;\n" ::: "memory");
}
__device__ __forceinline__ void ldm_x4(uint32_t* d, uint32_t addr) {
    asm volatile("ldmatrix.sync.aligned.m8n8.x4.shared.b16 {%0,%1,%2,%3}, [%4];"
                 : "=r"(d[0]), "=r"(d[1]), "=r"(d[2]), "=r"(d[3]) : "r"(addr));
}
__device__ __forceinline__ void mma_bf16(float* c, const uint32_t* a, uint32_t b0, uint32_t b1) {
    asm volatile("mma.sync.aligned.m16n8k16.row.col.f32.bf16.bf16.f32 "
                 "{%0,%1,%2,%3},{%4,%5,%6,%7},{%8,%9},{%0,%1,%2,%3};"
                 : "+f"(c[0]), "+f"(c[1]), "+f"(c[2]), "+f"(c[3])
                 : "r"(a[0]), "r"(a[1]), "r"(a[2]), "r"(a[3]), "r"(b0), "r"(b1));
}
__device__ __forceinline__ void spin_to(unsigned int* ctr, unsigned tgt) {
    unsigned cur;
    do {
        __nanosleep(64);
        asm volatile("ld.acquire.gpu.u32 %0, [%1];" : "=r"(cur) : "l"(ctr));
    } while (cur < tgt);
}

// ---------------------------------------------------------------------------
// Kernel A: convert x -> bf16, zero G/out, 144-CTA barrier, then GEMM
//           (upper-tri 64x64 tiles, splitK 4 — R7-proven mainloop)
// smem: A[2][64][144B]@0, B[2][64][144B]@18432
// ---------------------------------------------------------------------------
__global__ void __launch_bounds__(256) k_gemm(const float* __restrict__ x,
                                              float* __restrict__ out) {
    __shared__ __align__(16) char sm[36864];
    const int t = threadIdx.x;
    const int w = t >> 5, l = t & 31;
    const int bid = blockIdx.x;

    // Phase 1: convert + zero
    const int gi = bid * 256 + t;                 // 0..36863
    for (int idx = gi; idx < 524288; idx += NA * 256) {
        float4 v = reinterpret_cast<const float4*>(x)[idx];
        __nv_bfloat162 p0, p1;
        p0.x = __float2bfloat16(v.x); p0.y = __float2bfloat16(v.y);
        p1.x = __float2bfloat16(v.z); p1.y = __float2bfloat16(v.w);
        uint2 pk;
        pk.x = *reinterpret_cast<uint32_t*>(&p0);
        pk.y = *reinterpret_cast<uint32_t*>(&p1);
        reinterpret_cast<uint2*>(g_feats)[idx] = pk;
    }
    for (int idx = gi; idx < 65536; idx += NA * 256)
        reinterpret_cast<float4*>(g_G)[idx] = make_float4(0.f, 0.f, 0.f, 0.f);
    if (gi == 0) out[0] = 0.0f;

    __threadfence();
    __syncthreads();
    if (t == 0) {
        unsigned old = atomicAdd(&g_barA, 1u);
        unsigned tgt = old - (old % NA) + NA;
        spin_to(&g_barA, tgt);
    }
    __syncthreads();

    // Phase 2: GEMM
    const int tile = bid % 36;
    const int kz   = (bid / 36) * 1024;
    int rem = tile, bi = 0;
    while (rem >= 8 - bi) { rem -= 8 - bi; bi++; }
    const int bj = bi + rem;
    const int m0 = bi * 64, n0 = bj * 64;

    const int wm = (w >> 2) * 32;
    const int wn = (w & 3) * 16;

    float acc[2][2][4];
    #pragma unroll
    for (int a = 0; a < 2; a++)
      #pragma unroll
      for (int h = 0; h < 2; h++)
        #pragma unroll
        for (int q = 0; q < 4; q++) acc[a][h][q] = 0.f;

    const int lr = t >> 3;
    const int lc = (t & 7) * 8;
    const int lrow = l & 15;
    const int lkh  = (l >> 4) * 8;
    const uint32_t smA = smem_u32(sm);
    const uint32_t smB = smA + 18432;

    auto load_stage = [&](int ks, int buf) {
        const int kb = kz + ks * 64;
        #pragma unroll
        for (int p = 0; p < 2; p++) {
            const int row = lr + p * 32;
            cp_async16(smA + buf * 9216 + row * 144 + lc * 2,
                       &g_feats[(m0 + row) * HW + kb + lc]);
            cp_async16(smB + buf * 9216 + row * 144 + lc * 2,
                       &g_feats[(n0 + row) * HW + kb + lc]);
        }
        cp_commit();
    };

    load_stage(0, 0);
    for (int ks = 0; ks < 16; ks++) {
        const int buf = ks & 1;
        if (ks < 15) {
            load_stage(ks + 1, buf ^ 1);
            cp_wait<1>();
        } else {
            cp_wait<0>();
        }
        __syncthreads();

        #pragma unroll
        for (int k16 = 0; k16 < 4; k16++) {
            uint32_t afr[2][4], bfr[4];
            #pragma unroll
            for (int mt = 0; mt < 2; mt++)
                ldm_x4(afr[mt], smA + buf * 9216 + (wm + mt * 16 + lrow) * 144
                                    + (k16 * 16 + lkh) * 2);
            ldm_x4(bfr, smB + buf * 9216 + (wn + lrow) * 144
                            + (k16 * 16 + lkh) * 2);
            #pragma unroll
            for (int mt = 0; mt < 2; mt++) {
                mma_bf16(acc[mt][0], afr[mt], bfr[0], bfr[2]);
                mma_bf16(acc[mt][1], afr[mt], bfr[1], bfr[3]);
            }
        }
        __syncthreads();
    }

    const float s = 1.0f / 1048576.0f;
    const int g2 = l >> 2, cc = (l & 3) * 2;
    const bool mirror = (bi != bj);
    #pragma unroll
    for (int mt = 0; mt < 2; mt++)
      #pragma unroll
      for (int h = 0; h < 2; h++) {
        const int row = m0 + wm + mt * 16 + g2;
        const int col = n0 + wn + h * 8 + cc;
        const float v0 = acc[mt][h][0] * s;
        const float v1 = acc[mt][h][1] * s;
        const float v2 = acc[mt][h][2] * s;
        const float v3 = acc[mt][h][3] * s;
        atomicAdd(&g_G[row * CH + col],           v0);
        atomicAdd(&g_G[row * CH + col + 1],       v1);
        atomicAdd(&g_G[(row + 8) * CH + col],     v2);
        atomicAdd(&g_G[(row + 8) * CH + col + 1], v3);
        if (mirror) {
            atomicAdd(&g_G[col * CH + row],           v0);
            atomicAdd(&g_G[(col + 1) * CH + row],     v1);
            atomicAdd(&g_G[col * CH + row + 8],       v2);
            atomicAdd(&g_G[(col + 1) * CH + row + 8], v3);
        }
      }
}

// ---------------------------------------------------------------------------
// Kernel B: dedicated loss (R2-proven engine). CTA = (G-row r, j-half).
// loss += (sG[(i+t)&511] - T[i,j,t])^2 with perfectly coalesced T loads.
// ---------------------------------------------------------------------------
__global__ void __launch_bounds__(256) k_loss(const float* __restrict__ target,
                                              float* __restrict__ out) {
    __shared__ float sG[512];
    __shared__ float red[8];
    const int b  = blockIdx.x;       // 0..1023
    const int r  = b >> 1;
    const int j0 = (b & 1) * 128;
    const int t  = threadIdx.x;
    const int w  = t >> 5, l = t & 31;

    sG[t]       = g_G[r * CH + t];
    sG[t + 256] = g_G[r * CH + t + 256];
    __syncthreads();

    const float* tgt_t = target + t;
    float accum = 0.f;

    #pragma unroll 1
    for (int jb = j0; jb < j0 + 128; jb += 8) {
        float tv[8];
        #pragma unroll
        for (int u = 0; u < 8; u++) {
            const int j = jb + u;
            const int i = (r - j) & 511;
            tv[u] = __ldg(tgt_t + ((i << 16) + (j << 8)));
        }
        #pragma unroll
        for (int u = 0; u < 8; u++) {
            const int i = (r - (jb + u)) & 511;
            const float d = sG[(i + t) & 511] - tv[u];
            accum = fmaf(d, d, accum);
        }
    }

    #pragma unroll
    for (int o = 16; o > 0; o >>= 1)
        accum += __shfl_xor_sync(0xFFFFFFFFu, accum, o);
    if (l == 0) red[w] = accum;
    __syncthreads();
    if (t == 0) {
        float z = 0.f;
        #pragma unroll
        for (int ww = 0; ww < 8; ww++) z += red[ww];
        atomicAdd(out, z * SCALE);
    }
}

// ---------------------------------------------------------------------------
extern "C" void kernel_launch(void* const* d_in, const int* in_sizes, int n_in,
                              void* d_out, int out_size) {
    const float* x      = (const float*)d_in[0];   // (1,512,64,64) fp32
    const float* target = (const float*)d_in[1];   // (512,256,256) fp32
    float* out = (float*)d_out;

    k_gemm<<<NA, 256>>>(x, out);
    k_loss<<<1024, 256>>>(target, out);
}